// round 12
// baseline (speedup 1.0000x reference)
#include <cuda_runtime.h>

// SoftNCutsLoss: H=W=D=16, P=4096, K=4, RADIUS=5, O_I=10, O_X=4, N=2, C=1.
//
// W[p,q] = mask(sqd<=25) * exp(-(I_p-I_q)^2/10) * exp(-sqd/4)   (symmetric)
// num_k = sum_pq W A_k[p] A_k[q];  den_k = sum_pq W A_k[q]
// out[n] = 4 - sum_k num_k/(den_k+1e-8)
//
// R10 changes vs R5:
//  * A staged PLANAR (4x16KB planes) -> coalesced staging, no 16-way STS
//    bank conflicts from the old AoS transpose; loop uses 4x LDS.32.
//  * NGROUP 4 -> 9: 288 blocks, 2 blocks/SM (161KB smem), whole grid
//    resident in one wave -> 4 warps/SMSP to hide LDS/MUFU latency.
//  * table entry carries precomputed dq = dx*256+dy*16+dz.

#define P_VOX    4096
#define K_LAB    4
#define NGROUP   9
#define GSIZE    29            // 9 * 29 = 261
#define NOFF_PAD (NGROUP * GSIZE)
#define NBLK_X   16
#define NBATCH   2
#define TOTAL_BLOCKS (NBLK_X * NBATCH * NGROUP)   // 288

#define SMEM_I_BYTES 16384
#define SMEM_A_BYTES 65536
#define SMEM_BYTES   (SMEM_I_BYTES + SMEM_A_BYTES + 256)

// ---------------------------------------------------------------------------
// Compile-time half-space offset table.
// ---------------------------------------------------------------------------
struct TabT {
    int   x[NOFF_PAD], y[NOFF_PAD], z[NOFF_PAD], dq[NOFF_PAD];
    float c[NOFF_PAD];   // -sqd/4 * log2(e)
};

constexpr TabT gen_tab() {
    TabT t{};
    int cnt = 0;
    for (int dx = 0; dx <= 5; ++dx)
        for (int dy = -5; dy <= 5; ++dy)
            for (int dz = -5; dz <= 5; ++dz) {
                int sq = dx*dx + dy*dy + dz*dz;
                if (sq == 0 || sq > 25) continue;
                bool pos = (dx > 0) || (dx == 0 && (dy > 0 || (dy == 0 && dz > 0)));
                if (!pos) continue;
                t.x[cnt] = dx; t.y[cnt] = dy; t.z[cnt] = dz;
                t.dq[cnt] = dx * 256 + dy * 16 + dz;
                t.c[cnt] = -0.25f * 1.4426950408889634f * (float)sq;
                ++cnt;
            }
    for (; cnt < NOFF_PAD; ++cnt) {     // pad: always out-of-bounds
        t.x[cnt] = 100; t.y[cnt] = 0; t.z[cnt] = 0; t.dq[cnt] = 0; t.c[cnt] = 0.0f;
    }
    return t;
}

constexpr TabT h_tab = gen_tab();
__constant__ TabT c_tab = h_tab;

__device__ float    g_part[TOTAL_BLOCKS * 8];  // overwritten every run
__device__ unsigned g_ctr;                     // atomicInc wraps -> self-reset

// ---------------------------------------------------------------------------
__global__ __launch_bounds__(256)
void sncut_kernel(const float* __restrict__ labels,
                  const float* __restrict__ inputs,
                  float* __restrict__ out) {
    extern __shared__ char smem[];
    float* sI   = (float*)smem;
    float* sA0  = (float*)(smem + SMEM_I_BYTES);                 // planar planes
    float* sA1  = sA0 + P_VOX;
    float* sA2  = sA1 + P_VOX;
    float* sA3  = sA2 + P_VOX;
    float* sRed = (float*)(smem + SMEM_I_BYTES + SMEM_A_BYTES);
    __shared__ bool isLast;

    const int tid = threadIdx.x;
    const int n   = blockIdx.y;
    const float* I = inputs + n * P_VOX;
    const float* A = labels + n * K_LAB * P_VOX;

    // Stage I + A (planar, fully coalesced, conflict-free)
    {
        const float4* I4  = (const float4*)I;
        const float4* A4  = (const float4*)A;
        float4*       sI4 = (float4*)sI;
        float4*       sA4 = (float4*)sA0;
        #pragma unroll
        for (int i = 0; i < 4; ++i)
            sI4[tid + i * 256] = I4[tid + i * 256];
        #pragma unroll
        for (int i = 0; i < 16; ++i)
            sA4[tid + i * 256] = A4[tid + i * 256];
    }
    __syncthreads();

    const int p = (blockIdx.x << 8) + tid;
    const int z = p & 15, y = (p >> 4) & 15, x = p >> 8;
    const float Ip  = sI[p];
    const float Ap0 = sA0[p], Ap1 = sA1[p], Ap2 = sA2[p], Ap3 = sA3[p];
    const float C2  = -0.14426950408889634f;   // -0.1 * log2(e)

    float rs = 0.f, s0 = 0.f, s1 = 0.f, s2 = 0.f, s3 = 0.f;
    const int base = blockIdx.z * GSIZE;

    #pragma unroll
    for (int o = 0; o < GSIZE; ++o) {
        int qx = x + c_tab.x[base + o];               // uniform LDC
        int qy = y + c_tab.y[base + o];
        int qz = z + c_tab.z[base + o];
        bool ok = ((unsigned)(qx | qy | qz) < 16u);   // exact for 0..15 ranges
        int q = p + c_tab.dq[base + o];
        q = ok ? q : 0;
        float d   = sI[q] - Ip;
        float arg = fmaf(d * d, C2, c_tab.c[base + o]);
        arg = ok ? arg : -10000.0f;                   // ex2(-1e4) == 0
        float w;
        asm("ex2.approx.f32 %0, %1;" : "=f"(w) : "f"(arg));
        rs += w;
        s0 = fmaf(w, sA0[q], s0);
        s1 = fmaf(w, sA1[q], s1);
        s2 = fmaf(w, sA2[q], s2);
        s3 = fmaf(w, sA3[q], s3);
    }

    // Per-thread num/den contributions (diagonal only in group 0)
    const float cen = (blockIdx.z == 0) ? 1.0f : 0.0f;
    float v[8];
    v[0] = Ap0 * (2.f * s0 + cen * Ap0);
    v[1] = Ap1 * (2.f * s1 + cen * Ap1);
    v[2] = Ap2 * (2.f * s2 + cen * Ap2);
    v[3] = Ap3 * (2.f * s3 + cen * Ap3);
    v[4] = fmaf(Ap0, rs, s0) + cen * Ap0;
    v[5] = fmaf(Ap1, rs, s1) + cen * Ap1;
    v[6] = fmaf(Ap2, rs, s2) + cen * Ap2;
    v[7] = fmaf(Ap3, rs, s3) + cen * Ap3;

    // Warp reduce -> smem -> block partial
    #pragma unroll
    for (int j = 0; j < 8; ++j) {
        #pragma unroll
        for (int off = 16; off; off >>= 1)
            v[j] += __shfl_down_sync(0xffffffffu, v[j], off);
    }
    const int wid = tid >> 5, lane = tid & 31;
    if (lane == 0) {
        #pragma unroll
        for (int j = 0; j < 8; ++j) sRed[wid * 8 + j] = v[j];
    }
    __syncthreads();

    const int bid = (blockIdx.z * NBATCH + blockIdx.y) * NBLK_X + blockIdx.x;
    if (tid < 8) {
        float acc = 0.f;
        #pragma unroll
        for (int w8 = 0; w8 < 8; ++w8) acc += sRed[w8 * 8 + tid];
        g_part[bid * 8 + tid] = acc;
        __threadfence();                 // make partial device-visible
    }
    __syncthreads();

    // Last-block-done: atomicInc wraps at TOTAL_BLOCKS-1 -> self-resetting
    if (tid == 0) {
        unsigned old = atomicInc(&g_ctr, TOTAL_BLOCKS - 1);
        isLast = (old == TOTAL_BLOCKS - 1);
    }
    __syncthreads();

    if (isLast) {
        if (tid < 16) {
            int nn = tid >> 3, j = tid & 7;
            float acc = 0.f;
            #pragma unroll
            for (int gz = 0; gz < NGROUP; ++gz)
                #pragma unroll
                for (int gx = 0; gx < NBLK_X; ++gx)
                    acc += __ldcg(&g_part[((gz * NBATCH + nn) * NBLK_X + gx) * 8 + j]);
            sRed[64 + tid] = acc;
        }
        __syncthreads();
        if (tid < 2) {
            float loss = 0.f;
            #pragma unroll
            for (int k = 0; k < K_LAB; ++k)
                loss += sRed[64 + tid * 8 + k] / (sRed[64 + tid * 8 + 4 + k] + 1e-8f);
            out[tid] = 4.0f - loss;
        }
    }
}

// ---------------------------------------------------------------------------
extern "C" void kernel_launch(void* const* d_in, const int* in_sizes, int n_in,
                              void* d_out, int out_size) {
    // labels = 2*4*4096 = 32768 elems, inputs = 2*1*4096 = 8192 elems
    const float* labels;
    const float* inputs;
    if (in_sizes[0] == 2 * K_LAB * P_VOX) {
        labels = (const float*)d_in[0];
        inputs = (const float*)d_in[1];
    } else {
        labels = (const float*)d_in[1];
        inputs = (const float*)d_in[0];
    }
    float* out = (float*)d_out;

    cudaFuncSetAttribute(sncut_kernel,
                         cudaFuncAttributeMaxDynamicSharedMemorySize, SMEM_BYTES);

    dim3 grid(NBLK_X, NBATCH, NGROUP);
    sncut_kernel<<<grid, 256, SMEM_BYTES>>>(labels, inputs, out);
}

// round 14
// speedup vs baseline: 1.1544x; 1.1544x over previous
#include <cuda_runtime.h>

// SoftNCutsLoss: H=W=D=16, P=4096, K=4, RADIUS=5, O_I=10, O_X=4, N=2, C=1.
//
// W[p,q] = mask(sqd<=25) * exp(-(I_p-I_q)^2/10) * exp(-sqd/4)   (symmetric)
// num_k = sum_pq W A_k[p] A_k[q];  den_k = sum_pq W A_k[q]
// out[n] = 4 - sum_k num_k/(den_k+1e-8)
//
// R12 design: 2 voxels per thread (p, p+256 in a 512-voxel chunk) for 2x ILP
// in the stall-bound LDS/MUFU chain; x-coordinate uniform per block so the
// x bounds test is uniform and the y/z test is shared by the voxel pair.
// Grid 8 chunks x 2 n x 9 offset-groups = 144 blocks (~1 per SM, one wave).
// Planar A staging (conflict-free). unroll 5 (best ptxas pipelining, R5).

#define P_VOX    4096
#define K_LAB    4
#define NGROUP   9
#define GSIZE    30            // 9 * 30 = 270 >= 257
#define NOFF_PAD (NGROUP * GSIZE)
#define NBLK_X   8             // 512-voxel chunks
#define NBATCH   2
#define TOTAL_BLOCKS (NBLK_X * NBATCH * NGROUP)   // 144

#define SMEM_I_BYTES 16384
#define SMEM_A_BYTES 65536
#define SMEM_BYTES   (SMEM_I_BYTES + SMEM_A_BYTES + 256)

// ---------------------------------------------------------------------------
// Compile-time half-space offset table.
// ---------------------------------------------------------------------------
struct TabT {
    int   x[NOFF_PAD], y[NOFF_PAD], z[NOFF_PAD], dq[NOFF_PAD];
    float c[NOFF_PAD];   // -sqd/4 * log2(e)
};

constexpr TabT gen_tab() {
    TabT t{};
    int cnt = 0;
    for (int dx = 0; dx <= 5; ++dx)
        for (int dy = -5; dy <= 5; ++dy)
            for (int dz = -5; dz <= 5; ++dz) {
                int sq = dx*dx + dy*dy + dz*dz;
                if (sq == 0 || sq > 25) continue;
                bool pos = (dx > 0) || (dx == 0 && (dy > 0 || (dy == 0 && dz > 0)));
                if (!pos) continue;
                t.x[cnt] = dx; t.y[cnt] = dy; t.z[cnt] = dz;
                t.dq[cnt] = dx * 256 + dy * 16 + dz;
                t.c[cnt] = -0.25f * 1.4426950408889634f * (float)sq;
                ++cnt;
            }
    for (; cnt < NOFF_PAD; ++cnt) {     // pad: always out-of-bounds
        t.x[cnt] = 100; t.y[cnt] = 0; t.z[cnt] = 0; t.dq[cnt] = 0; t.c[cnt] = 0.0f;
    }
    return t;
}

constexpr TabT h_tab = gen_tab();
__constant__ TabT c_tab = h_tab;

__device__ float    g_part[TOTAL_BLOCKS * 8];  // overwritten every run
__device__ unsigned g_ctr;                     // atomicInc wraps -> self-reset

// ---------------------------------------------------------------------------
__global__ __launch_bounds__(256)
void sncut_kernel(const float* __restrict__ labels,
                  const float* __restrict__ inputs,
                  float* __restrict__ out) {
    extern __shared__ char smem[];
    float* sI   = (float*)smem;
    float* sA0  = (float*)(smem + SMEM_I_BYTES);   // planar planes
    float* sA1  = sA0 + P_VOX;
    float* sA2  = sA1 + P_VOX;
    float* sA3  = sA2 + P_VOX;
    float* sRed = (float*)(smem + SMEM_I_BYTES + SMEM_A_BYTES);
    __shared__ bool isLast;

    const int tid = threadIdx.x;
    const int n   = blockIdx.y;
    const float* I = inputs + n * P_VOX;
    const float* A = labels + n * K_LAB * P_VOX;

    // Stage I + A (planar, coalesced, conflict-free)
    {
        const float4* I4  = (const float4*)I;
        const float4* A4  = (const float4*)A;
        float4*       sI4 = (float4*)sI;
        float4*       sA4 = (float4*)sA0;
        #pragma unroll
        for (int i = 0; i < 4; ++i)
            sI4[tid + i * 256] = I4[tid + i * 256];
        #pragma unroll
        for (int i = 0; i < 16; ++i)
            sA4[tid + i * 256] = A4[tid + i * 256];
    }
    __syncthreads();

    // Voxel pair: pA = chunk*512 + tid (x = 2*chunk), pB = pA + 256 (x+1).
    const int pA = (blockIdx.x << 9) + tid;
    const int pB = pA + 256;
    const int z  = tid & 15, y = (tid >> 4) & 15;
    const int xA = blockIdx.x << 1;                 // uniform per block
    const float IpA = sI[pA], IpB = sI[pB];
    const float ApA0 = sA0[pA], ApA1 = sA1[pA], ApA2 = sA2[pA], ApA3 = sA3[pA];
    const float ApB0 = sA0[pB], ApB1 = sA1[pB], ApB2 = sA2[pB], ApB3 = sA3[pB];
    const float C2 = -0.14426950408889634f;         // -0.1 * log2(e)

    float rsA = 0.f, sA0a = 0.f, sA1a = 0.f, sA2a = 0.f, sA3a = 0.f;
    float rsB = 0.f, sB0a = 0.f, sB1a = 0.f, sB2a = 0.f, sB3a = 0.f;
    const int base = blockIdx.z * GSIZE;

    #pragma unroll 5
    for (int o = 0; o < GSIZE; ++o) {
        const int dx = c_tab.x[base + o];           // uniform LDC
        const int qy = y + c_tab.y[base + o];
        const int qz = z + c_tab.z[base + o];
        const bool okyz = ((unsigned)(qy | qz) < 16u);    // exact for 0..15
        const int  qxA  = xA + dx;                        // uniform
        const bool okA  = okyz & ((unsigned)qxA < 16u);
        const bool okB  = okyz & ((unsigned)(qxA + 1) < 16u);
        const int  dq   = c_tab.dq[base + o];
        const int  qA   = okA ? pA + dq : 0;
        const int  qB   = okB ? pB + dq : 0;
        const float cc  = c_tab.c[base + o];

        float dA = sI[qA] - IpA;
        float dB = sI[qB] - IpB;
        float argA = fmaf(dA * dA, C2, cc);
        float argB = fmaf(dB * dB, C2, cc);
        argA = okA ? argA : -10000.0f;              // ex2(-1e4) == 0
        argB = okB ? argB : -10000.0f;
        float wA, wB;
        asm("ex2.approx.f32 %0, %1;" : "=f"(wA) : "f"(argA));
        asm("ex2.approx.f32 %0, %1;" : "=f"(wB) : "f"(argB));

        rsA += wA;                                  rsB += wB;
        sA0a = fmaf(wA, sA0[qA], sA0a);             sB0a = fmaf(wB, sA0[qB], sB0a);
        sA1a = fmaf(wA, sA1[qA], sA1a);             sB1a = fmaf(wB, sA1[qB], sB1a);
        sA2a = fmaf(wA, sA2[qA], sA2a);             sB2a = fmaf(wB, sA2[qB], sB2a);
        sA3a = fmaf(wA, sA3[qA], sA3a);             sB3a = fmaf(wB, sA3[qB], sB3a);
    }

    // Per-thread num/den contributions for both voxels (diag only in group 0)
    const float cen = (blockIdx.z == 0) ? 1.0f : 0.0f;
    float v[8];
    v[0] = ApA0 * (2.f * sA0a + cen * ApA0) + ApB0 * (2.f * sB0a + cen * ApB0);
    v[1] = ApA1 * (2.f * sA1a + cen * ApA1) + ApB1 * (2.f * sB1a + cen * ApB1);
    v[2] = ApA2 * (2.f * sA2a + cen * ApA2) + ApB2 * (2.f * sB2a + cen * ApB2);
    v[3] = ApA3 * (2.f * sA3a + cen * ApA3) + ApB3 * (2.f * sB3a + cen * ApB3);
    v[4] = fmaf(ApA0, rsA, sA0a) + fmaf(ApB0, rsB, sB0a) + cen * (ApA0 + ApB0);
    v[5] = fmaf(ApA1, rsA, sA1a) + fmaf(ApB1, rsB, sB1a) + cen * (ApA1 + ApB1);
    v[6] = fmaf(ApA2, rsA, sA2a) + fmaf(ApB2, rsB, sB2a) + cen * (ApA2 + ApB2);
    v[7] = fmaf(ApA3, rsA, sA3a) + fmaf(ApB3, rsB, sB3a) + cen * (ApA3 + ApB3);

    // Warp reduce -> smem -> block partial
    #pragma unroll
    for (int j = 0; j < 8; ++j) {
        #pragma unroll
        for (int off = 16; off; off >>= 1)
            v[j] += __shfl_down_sync(0xffffffffu, v[j], off);
    }
    const int wid = tid >> 5, lane = tid & 31;
    if (lane == 0) {
        #pragma unroll
        for (int j = 0; j < 8; ++j) sRed[wid * 8 + j] = v[j];
    }
    __syncthreads();

    const int bid = (blockIdx.z * NBATCH + blockIdx.y) * NBLK_X + blockIdx.x;
    if (tid < 8) {
        float acc = 0.f;
        #pragma unroll
        for (int w8 = 0; w8 < 8; ++w8) acc += sRed[w8 * 8 + tid];
        g_part[bid * 8 + tid] = acc;
        __threadfence();                 // make partial device-visible
    }
    __syncthreads();

    // Last-block-done: atomicInc wraps at TOTAL_BLOCKS-1 -> self-resetting
    if (tid == 0) {
        unsigned old = atomicInc(&g_ctr, TOTAL_BLOCKS - 1);
        isLast = (old == TOTAL_BLOCKS - 1);
    }
    __syncthreads();

    if (isLast) {
        if (tid < 16) {
            int nn = tid >> 3, j = tid & 7;
            float acc = 0.f;
            #pragma unroll
            for (int gz = 0; gz < NGROUP; ++gz)
                #pragma unroll
                for (int gx = 0; gx < NBLK_X; ++gx)
                    acc += __ldcg(&g_part[((gz * NBATCH + nn) * NBLK_X + gx) * 8 + j]);
            sRed[64 + tid] = acc;
        }
        __syncthreads();
        if (tid < 2) {
            float loss = 0.f;
            #pragma unroll
            for (int k = 0; k < K_LAB; ++k)
                loss += sRed[64 + tid * 8 + k] / (sRed[64 + tid * 8 + 4 + k] + 1e-8f);
            out[tid] = 4.0f - loss;
        }
    }
}

// ---------------------------------------------------------------------------
extern "C" void kernel_launch(void* const* d_in, const int* in_sizes, int n_in,
                              void* d_out, int out_size) {
    // labels = 2*4*4096 = 32768 elems, inputs = 2*1*4096 = 8192 elems
    const float* labels;
    const float* inputs;
    if (in_sizes[0] == 2 * K_LAB * P_VOX) {
        labels = (const float*)d_in[0];
        inputs = (const float*)d_in[1];
    } else {
        labels = (const float*)d_in[1];
        inputs = (const float*)d_in[0];
    }
    float* out = (float*)d_out;

    cudaFuncSetAttribute(sncut_kernel,
                         cudaFuncAttributeMaxDynamicSharedMemorySize, SMEM_BYTES);

    dim3 grid(NBLK_X, NBATCH, NGROUP);
    sncut_kernel<<<grid, 256, SMEM_BYTES>>>(labels, inputs, out);
}

// round 15
// speedup vs baseline: 1.3692x; 1.1860x over previous
#include <cuda_runtime.h>

// SoftNCutsLoss: H=W=D=16, P=4096, K=4, RADIUS=5, O_I=10, O_X=4, N=2, C=1.
//
// W[p,q] = mask(sqd<=25) * exp(-(I_p-I_q)^2/10) * exp(-sqd/4)   (symmetric)
// num_k = sum_pq W A_k[p] A_k[q];  den_k = sum_pq W A_k[q]
// out[n] = 4 - sum_k num_k/(den_k+1e-8)
//
// R14: 4 voxels per thread (p, p+256, p+512, p+768; x = 4*chunk+vx uniform
// per block) -> 20 independent LDS + 4 MUFU chains per inner iteration.
// Evidence (R5/R10/R12): kernel is per-warp latency-bound; ILP helps,
// occupancy does not. Grid 4 chunks x 2 n x 18 offset-groups = 144 blocks.
// Planar A staging (conflict-free). Fast width-16-shuffle final reduce.

#define P_VOX    4096
#define K_LAB    4
#define NGROUP   18
#define GSIZE    15            // 18 * 15 = 270 >= 257
#define NOFF_PAD (NGROUP * GSIZE)
#define NBLK_X   4             // 1024-voxel chunks
#define NBATCH   2
#define BLK_PER_N (NGROUP * NBLK_X)               // 72
#define TOTAL_BLOCKS (BLK_PER_N * NBATCH)         // 144

#define SMEM_I_BYTES 16384
#define SMEM_A_BYTES 65536
#define SMEM_BYTES   (SMEM_I_BYTES + SMEM_A_BYTES + 512)

// ---------------------------------------------------------------------------
// Compile-time half-space offset table.
// ---------------------------------------------------------------------------
struct TabT {
    int   x[NOFF_PAD], y[NOFF_PAD], z[NOFF_PAD], dq[NOFF_PAD];
    float c[NOFF_PAD];   // -sqd/4 * log2(e)
};

constexpr TabT gen_tab() {
    TabT t{};
    int cnt = 0;
    for (int dx = 0; dx <= 5; ++dx)
        for (int dy = -5; dy <= 5; ++dy)
            for (int dz = -5; dz <= 5; ++dz) {
                int sq = dx*dx + dy*dy + dz*dz;
                if (sq == 0 || sq > 25) continue;
                bool pos = (dx > 0) || (dx == 0 && (dy > 0 || (dy == 0 && dz > 0)));
                if (!pos) continue;
                t.x[cnt] = dx; t.y[cnt] = dy; t.z[cnt] = dz;
                t.dq[cnt] = dx * 256 + dy * 16 + dz;
                t.c[cnt] = -0.25f * 1.4426950408889634f * (float)sq;
                ++cnt;
            }
    for (; cnt < NOFF_PAD; ++cnt) {     // pad: always out-of-bounds
        t.x[cnt] = 100; t.y[cnt] = 0; t.z[cnt] = 0; t.dq[cnt] = 0; t.c[cnt] = 0.0f;
    }
    return t;
}

constexpr TabT h_tab = gen_tab();
__constant__ TabT c_tab = h_tab;

__device__ float    g_part[TOTAL_BLOCKS * 8];  // overwritten every run
__device__ unsigned g_ctr;                     // atomicInc wraps -> self-reset

// ---------------------------------------------------------------------------
__global__ __launch_bounds__(256)
void sncut_kernel(const float* __restrict__ labels,
                  const float* __restrict__ inputs,
                  float* __restrict__ out) {
    extern __shared__ char smem[];
    float* sI   = (float*)smem;
    float* sA0  = (float*)(smem + SMEM_I_BYTES);   // planar planes
    float* sA1  = sA0 + P_VOX;
    float* sA2  = sA1 + P_VOX;
    float* sA3  = sA2 + P_VOX;
    float* sRed = (float*)(smem + SMEM_I_BYTES + SMEM_A_BYTES);
    __shared__ bool isLast;

    const int tid = threadIdx.x;
    const int n   = blockIdx.y;
    const float* I = inputs + n * P_VOX;
    const float* A = labels + n * K_LAB * P_VOX;

    // Stage I + A (planar, coalesced, conflict-free)
    {
        const float4* I4  = (const float4*)I;
        const float4* A4  = (const float4*)A;
        float4*       sI4 = (float4*)sI;
        float4*       sA4 = (float4*)sA0;
        #pragma unroll
        for (int i = 0; i < 4; ++i)
            sI4[tid + i * 256] = I4[tid + i * 256];
        #pragma unroll
        for (int i = 0; i < 16; ++i)
            sA4[tid + i * 256] = A4[tid + i * 256];
    }
    __syncthreads();

    // 4 voxels per thread: p0 + vx*256, x = 4*chunk + vx (uniform per block).
    const int p0 = (blockIdx.x << 10) + tid;
    const int z  = tid & 15, y = (tid >> 4) & 15;
    const int x0 = blockIdx.x << 2;                 // uniform per block
    const float C2 = -0.14426950408889634f;         // -0.1 * log2(e)

    float Ip[4], Ap[4][4], rs[4], sk[4][4];
    #pragma unroll
    for (int vx = 0; vx < 4; ++vx) {
        const int p = p0 + (vx << 8);
        Ip[vx] = sI[p];
        Ap[vx][0] = sA0[p]; Ap[vx][1] = sA1[p];
        Ap[vx][2] = sA2[p]; Ap[vx][3] = sA3[p];
        rs[vx] = 0.f;
        sk[vx][0] = sk[vx][1] = sk[vx][2] = sk[vx][3] = 0.f;
    }

    const int base = blockIdx.z * GSIZE;

    #pragma unroll 5
    for (int o = 0; o < GSIZE; ++o) {
        const int dx = c_tab.x[base + o];            // uniform LDC
        const int qy = y + c_tab.y[base + o];
        const int qz = z + c_tab.z[base + o];
        const bool okyz = ((unsigned)(qy | qz) < 16u);   // exact for 0..15
        const int  qx0  = x0 + dx;                       // uniform
        const int  dq   = c_tab.dq[base + o];
        const float cc  = c_tab.c[base + o];

        #pragma unroll
        for (int vx = 0; vx < 4; ++vx) {
            const bool ok = okyz & ((unsigned)(qx0 + vx) < 16u);
            const int  q  = ok ? (p0 + (vx << 8) + dq) : 0;
            float d   = sI[q] - Ip[vx];
            float arg = fmaf(d * d, C2, cc);
            arg = ok ? arg : -10000.0f;              // ex2(-1e4) == 0
            float w;
            asm("ex2.approx.f32 %0, %1;" : "=f"(w) : "f"(arg));
            rs[vx] += w;
            sk[vx][0] = fmaf(w, sA0[q], sk[vx][0]);
            sk[vx][1] = fmaf(w, sA1[q], sk[vx][1]);
            sk[vx][2] = fmaf(w, sA2[q], sk[vx][2]);
            sk[vx][3] = fmaf(w, sA3[q], sk[vx][3]);
        }
    }

    // Per-thread num/den contributions (diagonal only in group 0)
    const float cen = (blockIdx.z == 0) ? 1.0f : 0.0f;
    float v[8] = {0.f, 0.f, 0.f, 0.f, 0.f, 0.f, 0.f, 0.f};
    #pragma unroll
    for (int vx = 0; vx < 4; ++vx) {
        #pragma unroll
        for (int k = 0; k < 4; ++k) {
            v[k]     += Ap[vx][k] * (2.f * sk[vx][k] + cen * Ap[vx][k]);
            v[4 + k] += fmaf(Ap[vx][k], rs[vx], sk[vx][k]) + cen * Ap[vx][k];
        }
    }

    // Warp reduce -> smem -> block partial
    #pragma unroll
    for (int j = 0; j < 8; ++j) {
        #pragma unroll
        for (int off = 16; off; off >>= 1)
            v[j] += __shfl_down_sync(0xffffffffu, v[j], off);
    }
    const int wid = tid >> 5, lane = tid & 31;
    if (lane == 0) {
        #pragma unroll
        for (int j = 0; j < 8; ++j) sRed[wid * 8 + j] = v[j];
    }
    __syncthreads();

    // Per-n-contiguous partial layout: bid = n*72 + gz*NBLK_X + gx
    const int bid = n * BLK_PER_N + blockIdx.z * NBLK_X + blockIdx.x;
    if (tid < 8) {
        float acc = 0.f;
        #pragma unroll
        for (int w8 = 0; w8 < 8; ++w8) acc += sRed[w8 * 8 + tid];
        g_part[bid * 8 + tid] = acc;
        __threadfence();                 // make partial device-visible
    }
    __syncthreads();

    // Last-block-done: atomicInc wraps at TOTAL_BLOCKS-1 -> self-resetting
    if (tid == 0) {
        unsigned old = atomicInc(&g_ctr, TOTAL_BLOCKS - 1);
        isLast = (old == TOTAL_BLOCKS - 1);
    }
    __syncthreads();

    if (isLast) {
        // 16 output scalars (n,j); 16 threads each, width-16 shuffle reduce.
        const int g = tid >> 4, l16 = tid & 15;     // g: 0..15
        const int nn = g >> 3, j = g & 7;
        float acc = 0.f;
        #pragma unroll
        for (int m = l16; m < BLK_PER_N; m += 16)
            acc += __ldcg(&g_part[(nn * BLK_PER_N + m) * 8 + j]);
        #pragma unroll
        for (int off = 8; off; off >>= 1)
            acc += __shfl_down_sync(0xffffffffu, acc, off, 16);
        if (l16 == 0) sRed[64 + g] = acc;
        __syncthreads();
        if (tid < 2) {
            float loss = 0.f;
            #pragma unroll
            for (int k = 0; k < K_LAB; ++k)
                loss += sRed[64 + tid * 8 + k] / (sRed[64 + tid * 8 + 4 + k] + 1e-8f);
            out[tid] = 4.0f - loss;
        }
    }
}

// ---------------------------------------------------------------------------
extern "C" void kernel_launch(void* const* d_in, const int* in_sizes, int n_in,
                              void* d_out, int out_size) {
    // labels = 2*4*4096 = 32768 elems, inputs = 2*1*4096 = 8192 elems
    const float* labels;
    const float* inputs;
    if (in_sizes[0] == 2 * K_LAB * P_VOX) {
        labels = (const float*)d_in[0];
        inputs = (const float*)d_in[1];
    } else {
        labels = (const float*)d_in[1];
        inputs = (const float*)d_in[0];
    }
    float* out = (float*)d_out;

    cudaFuncSetAttribute(sncut_kernel,
                         cudaFuncAttributeMaxDynamicSharedMemorySize, SMEM_BYTES);

    dim3 grid(NBLK_X, NBATCH, NGROUP);
    sncut_kernel<<<grid, 256, SMEM_BYTES>>>(labels, inputs, out);
}